// round 10
// baseline (speedup 1.0000x reference)
#include <cuda_runtime.h>
#include <cstdint>

// SCM_19061064860184 — R10: neighbor-synchronized register scan with monotonic
// sequence-number flags (fixes R9's mbarrier parity-ABA deadlock).
// Per batch: 4-CTA cluster x 256 threads; 32 warps own 32 positions each + 16-halo
// per side. Every 8 ticks each warp publishes boundary strips to its two neighbors
// (smem / DSMEM) and syncs ONLY with them via per-side epoch counters.

#define NN 1024
#define TT 1024
#define NTH 256
#define CLC 4
#define NW 8
#define HB 16
#define FULLM 0xffffffffu

struct alignas(16) SmemT {
    float haloL[2][NW][2][16];     // [buf][warp][0=s,1=u][16] — left neighbor writes
    float haloR[2][NW][2][16];     // right neighbor writes
    uint32_t flagL[NW];            // epoch published by left neighbor
    uint32_t flagR[NW];            // epoch published by right neighbor
    float stage[NW][16][34];       // warp-private u staging (34: aligned + conflict-free)
};

__device__ float g_scr[8 * NN * TT];            // phase-A output (out2, transposed)
__device__ float g_R[8 * NN * TT + 4 * NN];     // precomputed R (+pad rows)

__device__ __forceinline__ uint32_t smem_u32(const void* p) {
    return (uint32_t)__cvta_generic_to_shared(p);
}

__device__ __forceinline__ void conv2acc(float& o0, float& o1,
    float L2, float L1, float v0, float v1, float R0, float R1, const float tp[5])
{
    o0 = fmaf(tp[0], L2, o0); o0 = fmaf(tp[1], L1, o0); o0 = fmaf(tp[2], v0, o0);
    o0 = fmaf(tp[3], v1, o0); o0 = fmaf(tp[4], R0, o0);
    o1 = fmaf(tp[0], L1, o1); o1 = fmaf(tp[1], v0, o1); o1 = fmaf(tp[2], v1, o1);
    o1 = fmaf(tp[3], R0, o1); o1 = fmaf(tp[4], R1, o1);
}

#define HALO2(v0, v1, L2, L1, R0, R1) do {        \
    L1 = __shfl_up_sync(FULLM, v1, 1);            \
    L2 = __shfl_up_sync(FULLM, v0, 1);            \
    R0 = __shfl_down_sync(FULLM, v0, 1);          \
    R1 = __shfl_down_sync(FULLM, v1, 1);          \
} while (0)

#define CLUSTER_ARRIVE() asm volatile("barrier.cluster.arrive.aligned;" ::: "memory")
#define CLUSTER_WAIT()   asm volatile("barrier.cluster.wait.aligned;"   ::: "memory")
#define FENCE_CLUSTER()  asm volatile("fence.acq_rel.cluster;" ::: "memory")

__device__ __forceinline__ void dsm_store2(const float* lptr, int trank, float a, float b)
{
    uint32_t la = smem_u32(lptr);
    uint32_t ra;
    asm volatile("mapa.shared::cluster.u32 %0, %1, %2;" : "=r"(ra) : "r"(la), "r"(trank));
    asm volatile("st.shared::cluster.v2.f32 [%0], {%1, %2};"
                 :: "r"(ra), "f"(a), "f"(b) : "memory");
}

__device__ __forceinline__ void flag_rel_local(const uint32_t* p, uint32_t v)
{
    asm volatile("st.release.cluster.shared::cta.u32 [%0], %1;"
                 :: "r"(smem_u32(p)), "r"(v) : "memory");
}

__device__ __forceinline__ void flag_rel_remote(const uint32_t* p, int trank, uint32_t v)
{
    uint32_t la = smem_u32(p);
    uint32_t ra;
    asm volatile("mapa.shared::cluster.u32 %0, %1, %2;" : "=r"(ra) : "r"(la), "r"(trank));
    asm volatile("st.release.cluster.shared::cluster.u32 [%0], %1;"
                 :: "r"(ra), "r"(v) : "memory");
}

__device__ __forceinline__ uint32_t flag_acq(const uint32_t* p)
{
    uint32_t v;
    asm volatile("ld.acquire.cluster.shared::cta.u32 %0, [%1];"
                 : "=r"(v) : "r"(smem_u32(p)) : "memory");
    return v;
}

// per-warp flush of 16 staged u-rows (i0..i0+15), transposed + reversed
__device__ __forceinline__ void flushw(const float (*stg)[34], float* __restrict__ O,
                                       int i0, int lane, int Pbase)
{
    const int qq = lane & 3;
    const int r0 = lane >> 2;
    const int cb = NN - 16 - i0 + 4 * qq;
    #pragma unroll
    for (int k = 0; k < 4; ++k) {
        const int p = r0 + 8 * k;
        float4 v;
        v.x = stg[15 - 4 * qq][p];
        v.y = stg[14 - 4 * qq][p];
        v.z = stg[13 - 4 * qq][p];
        v.w = stg[12 - 4 * qq][p];
        *reinterpret_cast<float4*>(O + (size_t)(Pbase + p) * NN + cb) = v;
    }
}

// s_t = convS_A(s_{t-1}) + R[t] ; u_0 = preB(s_0)+pBb ; u_t = convS_B(u_{t-1}) + convX_B(s_t) + bB
template <int COLTAPS>
__global__ void __launch_bounds__(NTH, 1) __cluster_dims__(CLC, 1, 1)
scan_kernel(float* __restrict__ OUT,
            const float* __restrict__ preBw, const float* __restrict__ preBb,
            const float* __restrict__ cAw,
            const float* __restrict__ cBw, const float* __restrict__ cBb)
{
    __shared__ SmemT sm;
    const int rank  = blockIdx.x & (CLC - 1);
    const int batch = blockIdx.x >> 2;
    const float* RIN = g_R + (size_t)batch * NN * TT;
    float* O = OUT + (size_t)batch * NN * TT;

    const int tid = threadIdx.x, w = tid >> 5, lane = tid & 31;
#define TI(k) (COLTAPS ? (5 * (k) + 2) : (10 + (k)))
    float aS[5], bS[5], bX[5], pB[5];
    #pragma unroll
    for (int k = 0; k < 5; ++k) {
        aS[k] = cAw[TI(k)];
        bS[k] = cBw[TI(k)];
        bX[k] = cBw[25 + TI(k)];
        pB[k] = preBw[TI(k)];
    }
    const float bB = cBb[0], pBb = preBb[0];
#undef TI

    // geometry: global warp wg owns positions [wg*32, wg*32+32)
    const int wg    = rank * NW + w;
    const int Pbase = wg * 32;
    const int g0    = Pbase - HB + 2 * lane;     // window slot pair base
    const bool inD0 = (g0 >= 0) && (g0 < NN);
    const bool inD1 = (g0 + 1 >= 0) && (g0 + 1 < NN);
    const bool own  = (lane >= 8 && lane < 24);
    const bool edgeW = (wg == 0) || (wg == CLC * NW - 1);
    const bool hasL = (wg != 0);
    const bool hasR = (wg != CLC * NW - 1);
    const int gr = g0 < 0 ? 0 : (g0 > NN - 2 ? NN - 2 : g0);   // float2-safe clamp
    float (*stg)[34] = sm.stage[w];

    // zero flags
    if (tid < NW) { sm.flagL[tid] = 0u; sm.flagR[tid] = 0u; }
    __syncthreads();
    CLUSTER_ARRIVE();     // flags zeroed cluster-wide before any remote publish
    CLUSTER_WAIT();

    // depth-4 register prefetch ring of R rows
    const float2* rp = reinterpret_cast<const float2*>(RIN + gr);
    const int RS = NN / 2;
    float2 ra  = rp[0];
    float2 rb  = rp[RS];
    float2 rr0 = rp[2 * RS];
    float2 rr1 = rp[3 * RS];
    float2 rr2 = rp[4 * RS];
    float2 rr3 = rp[5 * RS];
    const float2* pf = rp + 6 * RS;

    float s0, s1, u0, u1;

    // t = 0
    s0 = inD0 ? ra.x : 0.f;
    s1 = inD1 ? ra.y : 0.f;

    // t = 1: s_1 = convS(s_0) + R[1] ; u_0 = preB(s_0)
    {
        float sL2, sL1, sR0, sR1;
        HALO2(s0, s1, sL2, sL1, sR0, sR1);
        float a0 = rb.x, a1 = rb.y;
        conv2acc(a0, a1, sL2, sL1, s0, s1, sR0, sR1, aS);
        float c0 = pBb, c1 = pBb;
        conv2acc(c0, c1, sL2, sL1, s0, s1, sR0, sR1, pB);
        if (edgeW) {
            if (!inD0) { a0 = 0.f; c0 = 0.f; }
            if (!inD1) { a1 = 0.f; c1 = 0.f; }
        }
        s0 = a0; s1 = a1; u0 = c0; u1 = c1;
        if (own)
            *reinterpret_cast<float2*>(&stg[0][2 * (lane - 8)]) = make_float2(u0, u1);
    }

    auto body = [&](int t, float2& rc, const float2* ld) {
        float sL2, sL1, sR0, sR1, uL2, uL1, uR0, uR1;
        HALO2(s0, s1, sL2, sL1, sR0, sR1);
        HALO2(u0, u1, uL2, uL1, uR0, uR1);

        float a0 = rc.x, a1 = rc.y;
        conv2acc(a0, a1, sL2, sL1, s0, s1, sR0, sR1, aS);
        float cu0 = bB, cu1 = bB;
        conv2acc(cu0, cu1, uL2, uL1, u0, u1, uR0, uR1, bS);
        float cs0 = 0.f, cs1 = 0.f;
        conv2acc(cs0, cs1, sL2, sL1, s0, s1, sR0, sR1, bX);
        float c0 = cu0 + cs0, c1 = cu1 + cs1;

        if (edgeW) {
            if (!inD0) { a0 = 0.f; c0 = 0.f; }
            if (!inD1) { a1 = 0.f; c1 = 0.f; }
        }
        if (own)
            *reinterpret_cast<float2*>(&stg[(t - 1) & 15][2 * (lane - 8)]) = make_float2(c0, c1);
        s0 = a0; s1 = a1; u0 = c0; u1 = c1;

        rc = *ld;                                 // prefetch row t+4

        if ((t & 7) == 0) {                       // epoch: neighbor-only exchange
            const uint32_t e = (uint32_t)(t >> 3);   // 1..127, monotonic
            const int buf = (int)(e & 1);

            // publish: first 16 own -> left neighbor's right halo
            if (hasL && lane >= 8 && lane < 16) {
                const int i = 2 * (lane - 8);
                if (w > 0) {
                    *reinterpret_cast<float2*>(&sm.haloR[buf][w - 1][0][i]) = make_float2(s0, s1);
                    *reinterpret_cast<float2*>(&sm.haloR[buf][w - 1][1][i]) = make_float2(u0, u1);
                } else {
                    dsm_store2(&sm.haloR[buf][NW - 1][0][i], rank - 1, s0, s1);
                    dsm_store2(&sm.haloR[buf][NW - 1][1][i], rank - 1, u0, u1);
                }
                FENCE_CLUSTER();
            }
            // publish: last 16 own -> right neighbor's left halo
            if (hasR && lane >= 16 && lane < 24) {
                const int i = 2 * (lane - 16);
                if (w < NW - 1) {
                    *reinterpret_cast<float2*>(&sm.haloL[buf][w + 1][0][i]) = make_float2(s0, s1);
                    *reinterpret_cast<float2*>(&sm.haloL[buf][w + 1][1][i]) = make_float2(u0, u1);
                } else {
                    dsm_store2(&sm.haloL[buf][0][0][i], rank + 1, s0, s1);
                    dsm_store2(&sm.haloL[buf][0][1][i], rank + 1, u0, u1);
                }
                FENCE_CLUSTER();
            }
            __syncwarp();
            // flag stores (one lane per side), release semantics
            if (hasL && lane == 8) {
                if (w > 0) flag_rel_local(&sm.flagR[w - 1], e);
                else       flag_rel_remote(&sm.flagR[NW - 1], rank - 1, e);
            }
            if (hasR && lane == 16) {
                if (w < NW - 1) flag_rel_local(&sm.flagL[w + 1], e);
                else            flag_rel_remote(&sm.flagL[0], rank + 1, e);
            }

            // overlap local output flush with neighbor skew
            if ((t & 15) == 0) {
                __syncwarp();
                flushw(stg, O, t - 16, lane, Pbase);
            }

            // poll our two neighbors' epoch flags (uniform loop, all lanes)
            if (hasL | hasR) {
                while (true) {
                    uint32_t fL = hasL ? flag_acq(&sm.flagL[w]) : e;
                    uint32_t fR = hasR ? flag_acq(&sm.flagR[w]) : e;
                    if (fL >= e && fR >= e) break;
                }
            }
            // reload halos
            if (hasL && lane < 8) {
                const int i = 2 * lane;
                float2 sv = *reinterpret_cast<const float2*>(&sm.haloL[buf][w][0][i]);
                float2 uv = *reinterpret_cast<const float2*>(&sm.haloL[buf][w][1][i]);
                s0 = sv.x; s1 = sv.y; u0 = uv.x; u1 = uv.y;
            }
            if (hasR && lane >= 24) {
                const int i = 2 * (lane - 24);
                float2 sv = *reinterpret_cast<const float2*>(&sm.haloR[buf][w][0][i]);
                float2 uv = *reinterpret_cast<const float2*>(&sm.haloR[buf][w][1][i]);
                s0 = sv.x; s1 = sv.y; u0 = uv.x; u1 = uv.y;
            }
        }
    };

    // t = 2 .. 1021 in x4 groups, then 1022, 1023
    #pragma unroll 1
    for (int t = 2; t <= TT - 6; t += 4) {
        body(t,     rr0, pf);
        body(t + 1, rr1, pf + RS);
        body(t + 2, rr2, pf + 2 * RS);
        body(t + 3, rr3, pf + 3 * RS);
        pf += 4 * RS;
    }
    body(TT - 2, rr0, pf);
    body(TT - 1, rr1, pf + RS);

    // epilogue t = TT: u_{TT-1}
    {
        float sL2, sL1, sR0, sR1, uL2, uL1, uR0, uR1;
        HALO2(s0, s1, sL2, sL1, sR0, sR1);
        HALO2(u0, u1, uL2, uL1, uR0, uR1);
        float cu0 = bB, cu1 = bB;
        conv2acc(cu0, cu1, uL2, uL1, u0, u1, uR0, uR1, bS);
        float cs0 = 0.f, cs1 = 0.f;
        conv2acc(cs0, cs1, sL2, sL1, s0, s1, sR0, sR1, bX);
        float c0 = cu0 + cs0, c1 = cu1 + cs1;
        if (edgeW) { if (!inD0) c0 = 0.f; if (!inD1) c1 = 0.f; }
        if (own)
            *reinterpret_cast<float2*>(&stg[15][2 * (lane - 8)]) = make_float2(c0, c1);
        __syncwarp();
        flushw(stg, O, TT - 16, lane, Pbase);
    }
    // keep cluster resident until all remote traffic is consumed
    CLUSTER_ARRIVE();
    CLUSTER_WAIT();
}

// R[b][0][p] = pre_b + conv(pre taps, src[b][0]) ; R[b][t][p] = c_b + conv(c x-taps, src[b][t])
template <int COLTAPS, int PHASE>
__global__ void __launch_bounds__(256)
yprep(const float* __restrict__ srcparam,
      const float* __restrict__ pw, const float* __restrict__ pb,
      const float* __restrict__ cw, const float* __restrict__ cbias)
{
    const int r = blockIdx.x & (TT - 1);
    const int b = blockIdx.x >> 10;
    const float* src = (PHASE == 0 ? srcparam : (const float*)g_scr);
    const float* xr = src + ((size_t)b * TT + r) * NN;
    float* yr = g_R + ((size_t)b * TT + r) * NN;
    float tp[5], bias;
    #pragma unroll
    for (int k = 0; k < 5; ++k) {
        const int ti = COLTAPS ? (5 * k + 2) : (10 + k);
        tp[k] = (r == 0) ? pw[ti] : cw[25 + ti];
    }
    bias = (r == 0) ? pb[0] : cbias[0];
    const int p0 = threadIdx.x * 4;
    #pragma unroll
    for (int j = 0; j < 4; ++j) {
        const int p = p0 + j;
        float acc = bias;
        #pragma unroll
        for (int k = 0; k < 5; ++k) {
            const int q = p + k - 2;
            const float v = (q >= 0 && q < NN) ? __ldg(xr + q) : 0.f;
            acc = fmaf(tp[k], v, acc);
        }
        yr[p] = acc;
    }
}

extern "C" void kernel_launch(void* const* d_in, const int* in_sizes, int n_in,
                              void* d_out, int out_size)
{
    (void)in_sizes; (void)n_in; (void)out_size;
    const float* x   = (const float*)d_in[0];
    const float* p1w = (const float*)d_in[1];
    const float* p1b = (const float*)d_in[2];
    const float* p2w = (const float*)d_in[3];
    const float* p2b = (const float*)d_in[4];
    const float* p3w = (const float*)d_in[5];
    const float* p3b = (const float*)d_in[6];
    const float* p4w = (const float*)d_in[7];
    const float* p4b = (const float*)d_in[8];
    const float* c1w = (const float*)d_in[9];
    const float* c1b = (const float*)d_in[10];
    const float* c2w = (const float*)d_in[11];
    const float* c2b = (const float*)d_in[12];
    const float* c3w = (const float*)d_in[13];
    const float* c3b = (const float*)d_in[14];
    const float* c4w = (const float*)d_in[15];
    const float* c4b = (const float*)d_in[16];

    float* scr = nullptr;
    cudaGetSymbolAddress((void**)&scr, g_scr);

    // phase A: R = pre1/c1-x conv of x rows; scan (row taps) -> g_scr
    yprep<0, 0><<<8 * TT, 256>>>(x, p1w, p1b, c1w, c1b);
    scan_kernel<0><<<8 * CLC, NTH>>>(scr, p2w, p2b, c1w, c2w, c2b);
    // phase B: R = pre3/c3-x conv of scr rows; scan (col taps) -> out
    yprep<1, 1><<<8 * TT, 256>>>(nullptr, p3w, p3b, c3w, c3b);
    scan_kernel<1><<<8 * CLC, NTH>>>((float*)d_out, p4w, p4b, c3w, c4w, c4b);
}

// round 11
// speedup vs baseline: 1.2297x; 1.2297x over previous
#include <cuda_runtime.h>
#include <cstdint>

// SCM_19061064860184 — R11: R6 cluster scan with TWO batches per CTA.
// 4-CTA cluster x 512 threads; warps 0-7 = batch 2c, warps 8-15 = batch 2c+1.
// Each half owns 256 positions (warp: 32 own + 16-halo/side, 2 slots/thread).
// Global cluster.sync every 8 ticks; depth-4 R prefetch; PHASE-0 scan form.

#define NN 1024
#define TT 1024
#define NTH 512
#define CLC 4
#define OWNC 256              // positions per CTA-half
#define HB 16
#define EXW (OWNC + 2 * HB)   // 288
#define SW  (8 * 66)          // 528 padded stage width
#define FULLM 0xffffffffu

struct alignas(16) Smem {
    float sEx[2][2][EXW];       // [half][buf][slot]
    float uEx[2][2][EXW];
    float stage[2][32][SW];     // [half][row][slot]
};

__device__ float g_scr[8 * NN * TT];            // phase-A output (out2, transposed)
__device__ float g_R[8 * NN * TT + 4 * NN];     // precomputed R (+4 pad rows)

__device__ __forceinline__ void conv2acc(float& o0, float& o1,
    float L2, float L1, float v0, float v1, float R0, float R1, const float tp[5])
{
    o0 = fmaf(tp[0], L2, o0); o0 = fmaf(tp[1], L1, o0); o0 = fmaf(tp[2], v0, o0);
    o0 = fmaf(tp[3], v1, o0); o0 = fmaf(tp[4], R0, o0);
    o1 = fmaf(tp[0], L1, o1); o1 = fmaf(tp[1], v0, o1); o1 = fmaf(tp[2], v1, o1);
    o1 = fmaf(tp[3], R0, o1); o1 = fmaf(tp[4], R1, o1);
}

#define HALO2(v0, v1, L2, L1, R0, R1) do {        \
    L1 = __shfl_up_sync(FULLM, v1, 1);            \
    L2 = __shfl_up_sync(FULLM, v0, 1);            \
    R0 = __shfl_down_sync(FULLM, v0, 1);          \
    R1 = __shfl_down_sync(FULLM, v1, 1);          \
} while (0)

#define CLUSTER_ARRIVE() asm volatile("barrier.cluster.arrive.aligned;" ::: "memory")
#define CLUSTER_WAIT()   asm volatile("barrier.cluster.wait.aligned;"   ::: "memory")

__device__ __forceinline__ void dsm_store2(const float* lptr, int trank, float a, float b)
{
    uint32_t la = (uint32_t)__cvta_generic_to_shared(lptr);
    uint32_t ra;
    asm volatile("mapa.shared::cluster.u32 %0, %1, %2;" : "=r"(ra) : "r"(la), "r"(trank));
    asm volatile("st.shared::cluster.v2.f32 [%0], {%1, %2};"
                 :: "r"(ra), "f"(a), "f"(b) : "memory");
}

// flush 16 u-rows (indices i0..i0+15) for one half's 256 positions,
// transposed + reversed, float4 stores. tidh in [0,256).
__device__ __forceinline__ void flush16(const float (*stg)[SW], float* __restrict__ O,
                                        int i0, int tidh, int rank)
{
    const int q  = tidh & 3;
    const int rt = tidh >> 2;
    const int cb = NN - 4 - i0 - 4 * q;
    #pragma unroll
    for (int k = 0; k < 4; ++k) {
        const int pl = rt + (k << 6);                       // local position 0..255
        const int sa = (pl >> 5) * 66 + (pl & 31) + 16;     // stage column of pl
        float4 v;
        v.x = stg[(i0 + 4 * q + 3) & 31][sa];
        v.y = stg[(i0 + 4 * q + 2) & 31][sa];
        v.z = stg[(i0 + 4 * q + 1) & 31][sa];
        v.w = stg[(i0 + 4 * q + 0) & 31][sa];
        *reinterpret_cast<float4*>(O + (size_t)(rank * OWNC + pl) * NN + cb) = v;
    }
}

// PHASE 0: writes g_scr; PHASE 1: writes OUTparam. R always g_R.
// s_t = convS_A(s_{t-1}) + R[t] ; u_0 = preB(s_0)+pBb ; u_t = convS_B(u_{t-1}) + convX_B(s_t) + bB
template <int COLTAPS, int PHASE>
__global__ void __launch_bounds__(NTH, 1) __cluster_dims__(CLC, 1, 1)
scan_kernel(float* __restrict__ OUTparam,
            const float* __restrict__ preBw, const float* __restrict__ preBb,
            const float* __restrict__ cAw,
            const float* __restrict__ cBw, const float* __restrict__ cBb)
{
    extern __shared__ char raw[];
    Smem* sm = reinterpret_cast<Smem*>(raw);
    const int rank  = blockIdx.x & (CLC - 1);
    const int tid   = threadIdx.x;
    const int h     = tid >> 8;                  // CTA half = which batch
    const int tidh  = tid & 255;
    const int w     = tidh >> 5;                 // warp within half, 0..7
    const int lane  = tid & 31;
    const int batch = (blockIdx.x >> 2) * 2 + h;

    const float* RIN = g_R + (size_t)batch * NN * TT;
    float* O = (PHASE == 0 ? g_scr : OUTparam) + (size_t)batch * NN * TT;

#define TI(k) (COLTAPS ? (5 * (k) + 2) : (10 + (k)))
    float aS[5], bS[5], bX[5], pB[5];
    #pragma unroll
    for (int k = 0; k < 5; ++k) {
        aS[k] = cAw[TI(k)];
        bS[k] = cBw[TI(k)];
        bX[k] = cBw[25 + TI(k)];
        pB[k] = preBw[TI(k)];
    }
    const float bB = cBb[0], pBb = preBb[0];
#undef TI

    // geometry (within this half's batch)
    const int off0 = w * 32 + 2 * lane;          // window coord of slot 0 (0..286)
    const int g0   = rank * OWNC - HB + off0;    // global position of slot 0
    const bool inD0 = (g0 >= 0) && (g0 < NN);
    const bool inD1 = (g0 + 1 >= 0) && (g0 + 1 < NN);
    const bool own  = (lane >= 8 && lane < 24);
    const bool edgeW = (rank == 0 && w == 0) || (rank == CLC - 1 && w == 7);
    const bool remL = (rank > 0) && (w == 0) && (lane >= 8 && lane < 16);
    const bool remR = (rank < CLC - 1) && (w == 7) && (lane >= 16 && lane < 24);
    const int gr = g0 < 0 ? 0 : (g0 > NN - 2 ? NN - 2 : g0);   // float2-safe clamp
    const int stb = w * 66 + 2 * lane;
    const float (*stg)[SW] = sm->stage[h];

    // zero exchange buffers (edge-halo slots stay 0 forever = domain padding)
    {
        float* p0 = &sm->sEx[0][0][0];
        float* p1 = &sm->uEx[0][0][0];
        for (int i = tid; i < 2 * 2 * EXW; i += NTH) { p0[i] = 0.f; p1[i] = 0.f; }
    }
    __syncthreads();
    CLUSTER_ARRIVE();     // all exchange buffers zeroed before any peer DSMEM store
    CLUSTER_WAIT();

    // depth-4 prefetch ring; rows 0..5 in ra,rb,rr0..rr3
    const float2* rp = reinterpret_cast<const float2*>(RIN + gr);
    const int RS = NN / 2;
    float2 ra  = rp[0];
    float2 rb  = rp[RS];
    float2 rr0 = rp[2 * RS];
    float2 rr1 = rp[3 * RS];
    float2 rr2 = rp[4 * RS];
    float2 rr3 = rp[5 * RS];
    const float2* pf = rp + 6 * RS;              // next row to prefetch (row 6)

    float s0, s1, u0, u1;

    // t = 0
    s0 = inD0 ? ra.x : 0.f;
    s1 = inD1 ? ra.y : 0.f;

    // t = 1: s_1 = convS(s_0) + R[1] ; u_0 = preB(s_0)
    {
        float sL2, sL1, sR0, sR1;
        HALO2(s0, s1, sL2, sL1, sR0, sR1);
        float a0 = rb.x, a1 = rb.y;
        conv2acc(a0, a1, sL2, sL1, s0, s1, sR0, sR1, aS);
        float c0 = pBb, c1 = pBb;
        conv2acc(c0, c1, sL2, sL1, s0, s1, sR0, sR1, pB);
        if (edgeW) {
            if (!inD0) { a0 = 0.f; c0 = 0.f; }
            if (!inD1) { a1 = 0.f; c1 = 0.f; }
        }
        s0 = a0; s1 = a1; u0 = c0; u1 = c1;
        *reinterpret_cast<float2*>(&sm->stage[h][0][stb]) = make_float2(u0, u1);
    }

    // main body: tick t computes s_t and u_{t-1}; refills ring slot with row t+4
    auto body = [&](int t, float2& rc, const float2* ld) {
        float sL2, sL1, sR0, sR1, uL2, uL1, uR0, uR1;
        HALO2(s0, s1, sL2, sL1, sR0, sR1);
        HALO2(u0, u1, uL2, uL1, uR0, uR1);

        float a0 = rc.x, a1 = rc.y;
        conv2acc(a0, a1, sL2, sL1, s0, s1, sR0, sR1, aS);
        float cu0 = bB, cu1 = bB;                         // u-tap chain
        conv2acc(cu0, cu1, uL2, uL1, u0, u1, uR0, uR1, bS);
        float cs0 = 0.f, cs1 = 0.f;                       // s-tap chain (independent)
        conv2acc(cs0, cs1, sL2, sL1, s0, s1, sR0, sR1, bX);
        float c0 = cu0 + cs0, c1 = cu1 + cs1;

        if (edgeW) {
            if (!inD0) { a0 = 0.f; c0 = 0.f; }
            if (!inD1) { a1 = 0.f; c1 = 0.f; }
        }
        const int sr = (t - 1) & 31;
        *reinterpret_cast<float2*>(&sm->stage[h][sr][stb]) = make_float2(c0, c1);
        s0 = a0; s1 = a1; u0 = c0; u1 = c1;

        rc = *ld;                                          // prefetch row t+4

        if ((t & 7) == 0) {                       // exchange epoch
            const int buf = (t >> 3) & 1;
            if (own) {
                *reinterpret_cast<float2*>(&sm->sEx[h][buf][off0]) = make_float2(s0, s1);
                *reinterpret_cast<float2*>(&sm->uEx[h][buf][off0]) = make_float2(u0, u1);
            }
            if (remL) {                           // my first 16 own -> left CTA's right halo
                dsm_store2(&sm->sEx[h][buf][off0 + OWNC], rank - 1, s0, s1);
                dsm_store2(&sm->uEx[h][buf][off0 + OWNC], rank - 1, u0, u1);
            }
            if (remR) {                           // my last 16 own -> right CTA's left halo
                dsm_store2(&sm->sEx[h][buf][off0 - OWNC], rank + 1, s0, s1);
                dsm_store2(&sm->uEx[h][buf][off0 - OWNC], rank + 1, u0, u1);
            }
            __syncthreads();                      // local stage + sEx visible CTA-wide
            CLUSTER_ARRIVE();
            if ((t & 15) == 0) flush16(stg, O, t - 16, tidh, rank);   // overlap with wait
            CLUSTER_WAIT();
            if (!own) {
                if (inD0) {
                    float2 sv = *reinterpret_cast<const float2*>(&sm->sEx[h][buf][off0]);
                    float2 uv = *reinterpret_cast<const float2*>(&sm->uEx[h][buf][off0]);
                    s0 = sv.x; u0 = uv.x;
                    if (inD1) { s1 = sv.y; u1 = uv.y; }
                } else if (inD1) {
                    s1 = sm->sEx[h][buf][off0 + 1]; u1 = sm->uEx[h][buf][off0 + 1];
                }
            }
        }
    };

    // t = 2 .. 1021, unrolled x4 (255 iterations), then 1022, 1023
    #pragma unroll 1
    for (int t = 2; t <= TT - 6; t += 4) {
        body(t,     rr0, pf);
        body(t + 1, rr1, pf + RS);
        body(t + 2, rr2, pf + 2 * RS);
        body(t + 3, rr3, pf + 3 * RS);
        pf += 4 * RS;
    }
    body(TT - 2, rr0, pf);           // prefetches padded rows 1026/1027
    body(TT - 1, rr1, pf + RS);

    // epilogue t = TT: u_{TT-1}
    {
        float sL2, sL1, sR0, sR1, uL2, uL1, uR0, uR1;
        HALO2(s0, s1, sL2, sL1, sR0, sR1);
        HALO2(u0, u1, uL2, uL1, uR0, uR1);
        float cu0 = bB, cu1 = bB;
        conv2acc(cu0, cu1, uL2, uL1, u0, u1, uR0, uR1, bS);
        float cs0 = 0.f, cs1 = 0.f;
        conv2acc(cs0, cs1, sL2, sL1, s0, s1, sR0, sR1, bX);
        float c0 = cu0 + cs0, c1 = cu1 + cs1;
        if (edgeW) { if (!inD0) c0 = 0.f; if (!inD1) c1 = 0.f; }
        *reinterpret_cast<float2*>(&sm->stage[h][31][stb]) = make_float2(c0, c1);
        __syncthreads();
        flush16(stg, O, TT - 16, tidh, rank);
    }
}

// R[b][0][p] = pre_b + conv(pre taps, src[b][0]) ; R[b][t][p] = c_b + conv(c x-taps, src[b][t])
template <int COLTAPS, int PHASE>
__global__ void __launch_bounds__(256)
yprep(const float* __restrict__ srcparam,
      const float* __restrict__ pw, const float* __restrict__ pb,
      const float* __restrict__ cw, const float* __restrict__ cbias)
{
    const int r = blockIdx.x & (TT - 1);
    const int b = blockIdx.x >> 10;
    const float* src = (PHASE == 0 ? srcparam : (const float*)g_scr);
    const float* xr = src + ((size_t)b * TT + r) * NN;
    float* yr = g_R + ((size_t)b * TT + r) * NN;
    float tp[5], bias;
    #pragma unroll
    for (int k = 0; k < 5; ++k) {
        const int ti = COLTAPS ? (5 * k + 2) : (10 + k);
        tp[k] = (r == 0) ? pw[ti] : cw[25 + ti];
    }
    bias = (r == 0) ? pb[0] : cbias[0];
    const int p0 = threadIdx.x * 4;
    #pragma unroll
    for (int j = 0; j < 4; ++j) {
        const int p = p0 + j;
        float acc = bias;
        #pragma unroll
        for (int k = 0; k < 5; ++k) {
            const int q = p + k - 2;
            const float v = (q >= 0 && q < NN) ? __ldg(xr + q) : 0.f;
            acc = fmaf(tp[k], v, acc);
        }
        yr[p] = acc;
    }
}

extern "C" void kernel_launch(void* const* d_in, const int* in_sizes, int n_in,
                              void* d_out, int out_size)
{
    (void)in_sizes; (void)n_in; (void)out_size;
    const float* x   = (const float*)d_in[0];
    const float* p1w = (const float*)d_in[1];
    const float* p1b = (const float*)d_in[2];
    const float* p2w = (const float*)d_in[3];
    const float* p2b = (const float*)d_in[4];
    const float* p3w = (const float*)d_in[5];
    const float* p3b = (const float*)d_in[6];
    const float* p4w = (const float*)d_in[7];
    const float* p4b = (const float*)d_in[8];
    const float* c1w = (const float*)d_in[9];
    const float* c1b = (const float*)d_in[10];
    const float* c2w = (const float*)d_in[11];
    const float* c2b = (const float*)d_in[12];
    const float* c3w = (const float*)d_in[13];
    const float* c3b = (const float*)d_in[14];
    const float* c4w = (const float*)d_in[15];
    const float* c4b = (const float*)d_in[16];

    cudaFuncSetAttribute(scan_kernel<0, 0>, cudaFuncAttributeMaxDynamicSharedMemorySize, (int)sizeof(Smem));
    cudaFuncSetAttribute(scan_kernel<1, 1>, cudaFuncAttributeMaxDynamicSharedMemorySize, (int)sizeof(Smem));

    // phase A: R = pre1/c1-x conv of x rows; scan (row taps) -> g_scr
    yprep<0, 0><<<8 * TT, 256>>>(x, p1w, p1b, c1w, c1b);
    scan_kernel<0, 0><<<4 * CLC, NTH, sizeof(Smem)>>>(nullptr, p2w, p2b, c1w, c2w, c2b);
    // phase B: R = pre3/c3-x conv of scr rows; scan (col taps) -> out
    yprep<1, 1><<<8 * TT, 256>>>(nullptr, p3w, p3b, c3w, c3b);
    scan_kernel<1, 1><<<4 * CLC, NTH, sizeof(Smem)>>>((float*)d_out, p4w, p4b, c3w, c4w, c4b);
}

// round 12
// speedup vs baseline: 1.5893x; 1.2924x over previous
#include <cuda_runtime.h>
#include <cstdint>

// SCM_19061064860184 — R12: R6 cluster scan + f32x2 packed math + warp-private
// coalesced flush + no __syncthreads (cluster barrier subsumes).
// Per batch: 4-CTA cluster x 256 threads; warp owns 32 positions + 16-halo/side
// (window 64, 2 slots/thread). Global cluster.sync every 8 ticks; depth-4 R
// prefetch; PHASE-0 scan form with yprep-precomputed input contribution.

#define NN 1024
#define TT 1024
#define NTH 256
#define CLC 4
#define OWNC 256
#define HB 16
#define EXW (OWNC + 2 * HB)   // 288
#define SW  546               // stage stride: 8*66=528 used; 546%32==2 -> conflict-free flush
#define FULLM 0xffffffffu

struct alignas(16) Smem {
    float sEx[2][EXW];
    float uEx[2][EXW];
    float stage[32][SW];
};

__device__ float g_scr[8 * NN * TT];            // phase-A output (out2, transposed)
__device__ float g_R[8 * NN * TT + 4 * NN];     // precomputed R (+4 pad rows)

// ---------- packed f32x2 helpers ----------
__device__ __forceinline__ uint64_t pk2(float lo, float hi) {
    uint64_t r; asm("mov.b64 %0, {%1, %2};" : "=l"(r) : "f"(lo), "f"(hi)); return r;
}
__device__ __forceinline__ void upk2(uint64_t v, float& lo, float& hi) {
    asm("mov.b64 {%0, %1}, %2;" : "=f"(lo), "=f"(hi) : "l"(v));
}
__device__ __forceinline__ uint64_t fma2(uint64_t a, uint64_t b, uint64_t c) {
    uint64_t d; asm("fma.rn.f32x2 %0, %1, %2, %3;" : "=l"(d) : "l"(a), "l"(b), "l"(c)); return d;
}
__device__ __forceinline__ uint64_t add2(uint64_t a, uint64_t b) {
    uint64_t d; asm("add.rn.f32x2 %0, %1, %2;" : "=l"(d) : "l"(a), "l"(b)); return d;
}

// scalar conv for prologue/epilogue (bit-identical per-output order to packed path)
__device__ __forceinline__ void conv2acc(float& o0, float& o1,
    float L2, float L1, float v0, float v1, float R0, float R1, const float tp[5])
{
    o0 = fmaf(tp[0], L2, o0); o0 = fmaf(tp[1], L1, o0); o0 = fmaf(tp[2], v0, o0);
    o0 = fmaf(tp[3], v1, o0); o0 = fmaf(tp[4], R0, o0);
    o1 = fmaf(tp[0], L1, o1); o1 = fmaf(tp[1], v0, o1); o1 = fmaf(tp[2], v1, o1);
    o1 = fmaf(tp[3], R0, o1); o1 = fmaf(tp[4], R1, o1);
}

#define HALO2(v0, v1, L2, L1, R0, R1) do {        \
    L1 = __shfl_up_sync(FULLM, v1, 1);            \
    L2 = __shfl_up_sync(FULLM, v0, 1);            \
    R0 = __shfl_down_sync(FULLM, v0, 1);          \
    R1 = __shfl_down_sync(FULLM, v1, 1);          \
} while (0)

#define CLUSTER_ARRIVE() asm volatile("barrier.cluster.arrive.aligned;" ::: "memory")
#define CLUSTER_WAIT()   asm volatile("barrier.cluster.wait.aligned;"   ::: "memory")

__device__ __forceinline__ void dsm_store2(const float* lptr, int trank, float a, float b)
{
    uint32_t la = (uint32_t)__cvta_generic_to_shared(lptr);
    uint32_t ra;
    asm volatile("mapa.shared::cluster.u32 %0, %1, %2;" : "=r"(ra) : "r"(la), "r"(trank));
    asm volatile("st.shared::cluster.v2.f32 [%0], {%1, %2};"
                 :: "r"(ra), "f"(a), "f"(b) : "memory");
}

// warp-private flush of 16 u-rows (i0..i0+15) for warp w's 32 own positions.
// 4 lanes share one row (64B segment) -> 8 gmem lines per STG.128 instead of 32.
__device__ __forceinline__ void flushw(const float (*stg)[SW], float* __restrict__ O,
                                       int i0, int w, int lane, int rank)
{
    const int q = lane & 3;
    const int r = lane >> 2;
    const int cb = NN - 4 - i0 - 4 * q;
    #pragma unroll
    for (int k = 0; k < 4; ++k) {
        const int pl = w * 32 + r + 8 * k;           // this warp's own local position
        const int sa = w * 66 + (r + 8 * k) + 16;    // stage column of pl
        float4 v;
        v.x = stg[(i0 + 4 * q + 3) & 31][sa];
        v.y = stg[(i0 + 4 * q + 2) & 31][sa];
        v.z = stg[(i0 + 4 * q + 1) & 31][sa];
        v.w = stg[(i0 + 4 * q + 0) & 31][sa];
        *reinterpret_cast<float4*>(O + (size_t)(rank * OWNC + pl) * NN + cb) = v;
    }
}

// PHASE 0: writes g_scr; PHASE 1: writes OUTparam. R always g_R.
// s_t = convS_A(s_{t-1}) + R[t] ; u_0 = preB(s_0)+pBb ; u_t = convS_B(u_{t-1}) + convX_B(s_t) + bB
template <int COLTAPS, int PHASE>
__global__ void __launch_bounds__(NTH, 1) __cluster_dims__(CLC, 1, 1)
scan_kernel(float* __restrict__ OUTparam,
            const float* __restrict__ preBw, const float* __restrict__ preBb,
            const float* __restrict__ cAw,
            const float* __restrict__ cBw, const float* __restrict__ cBb)
{
    extern __shared__ char raw[];
    Smem* sm = reinterpret_cast<Smem*>(raw);
    const int rank  = blockIdx.x & (CLC - 1);
    const int batch = blockIdx.x >> 2;
    const float* RIN = g_R + (size_t)batch * NN * TT;
    float* O = (PHASE == 0 ? g_scr : OUTparam) + (size_t)batch * NN * TT;

    const int tid = threadIdx.x, w = tid >> 5, lane = tid & 31;
#define TI(k) (COLTAPS ? (5 * (k) + 2) : (10 + (k)))
    float aS[5], bS[5], bX[5], pB[5];
    uint64_t aSp[5], bSp[5], bXp[5];
    #pragma unroll
    for (int k = 0; k < 5; ++k) {
        aS[k] = cAw[TI(k)];
        bS[k] = cBw[TI(k)];
        bX[k] = cBw[25 + TI(k)];
        pB[k] = preBw[TI(k)];
        aSp[k] = pk2(aS[k], aS[k]);
        bSp[k] = pk2(bS[k], bS[k]);
        bXp[k] = pk2(bX[k], bX[k]);
    }
    const float bB = cBb[0], pBb = preBb[0];
    const uint64_t bBp = pk2(bB, bB);
    const uint64_t Z64 = pk2(0.f, 0.f);
#undef TI

    // geometry
    const int off0 = w * 32 + 2 * lane;          // CTA-window coord of slot 0 (0..286)
    const int g0   = rank * OWNC - HB + off0;    // global position of slot 0
    const bool inD0 = (g0 >= 0) && (g0 < NN);
    const bool inD1 = (g0 + 1 >= 0) && (g0 + 1 < NN);
    const bool own  = (lane >= 8 && lane < 24);
    const bool edgeW = (rank == 0 && w == 0) || (rank == CLC - 1 && w == 7);
    const bool remL = (rank > 0) && (w == 0) && (lane >= 8 && lane < 16);
    const bool remR = (rank < CLC - 1) && (w == 7) && (lane >= 16 && lane < 24);
    const int gr = g0 < 0 ? 0 : (g0 > NN - 2 ? NN - 2 : g0);   // float2-safe clamp
    const int stb = w * 66 + 2 * lane;
    const float (*stg)[SW] = sm->stage;

    // zero exchange buffers (edge-halo slots stay 0 forever = domain padding)
    {
        float* p0 = &sm->sEx[0][0];
        float* p1 = &sm->uEx[0][0];
        for (int i = tid; i < 2 * EXW; i += NTH) { p0[i] = 0.f; p1[i] = 0.f; }
    }
    CLUSTER_ARRIVE();     // release: zeroing visible cluster-wide (incl. own CTA)
    CLUSTER_WAIT();

    // depth-4 prefetch ring; rows 0..5 in ra,rb,rr0..rr3
    const float2* rp = reinterpret_cast<const float2*>(RIN + gr);
    const int RS = NN / 2;
    float2 ra  = rp[0];
    float2 rb  = rp[RS];
    float2 rr0 = rp[2 * RS];
    float2 rr1 = rp[3 * RS];
    float2 rr2 = rp[4 * RS];
    float2 rr3 = rp[5 * RS];
    const float2* pf = rp + 6 * RS;              // next row to prefetch (row 6)

    float s0, s1, u0, u1;

    // t = 0
    s0 = inD0 ? ra.x : 0.f;
    s1 = inD1 ? ra.y : 0.f;

    // t = 1: s_1 = convS(s_0) + R[1] ; u_0 = preB(s_0)  (scalar path)
    {
        float sL2, sL1, sR0, sR1;
        HALO2(s0, s1, sL2, sL1, sR0, sR1);
        float a0 = rb.x, a1 = rb.y;
        conv2acc(a0, a1, sL2, sL1, s0, s1, sR0, sR1, aS);
        float c0 = pBb, c1 = pBb;
        conv2acc(c0, c1, sL2, sL1, s0, s1, sR0, sR1, pB);
        if (edgeW) {
            if (!inD0) { a0 = 0.f; c0 = 0.f; }
            if (!inD1) { a1 = 0.f; c1 = 0.f; }
        }
        s0 = a0; s1 = a1; u0 = c0; u1 = c1;
        *reinterpret_cast<float2*>(&sm->stage[0][stb]) = make_float2(u0, u1);
    }

    // main body: tick t computes s_t and u_{t-1} (packed f32x2 math)
    auto body = [&](int t, float2& rc, const float2* ld) {
        float sL2, sL1, sR0, sR1, uL2, uL1, uR0, uR1;
        HALO2(s0, s1, sL2, sL1, sR0, sR1);
        HALO2(u0, u1, uL2, uL1, uR0, uR1);

        // packed shifted windows (s shared by aS- and bX-convs)
        const uint64_t Ps0 = pk2(sL2, sL1), Ps1 = pk2(sL1, s0), Ps2 = pk2(s0, s1),
                       Ps3 = pk2(s1, sR0), Ps4 = pk2(sR0, sR1);
        const uint64_t Pu0 = pk2(uL2, uL1), Pu1 = pk2(uL1, u0), Pu2 = pk2(u0, u1),
                       Pu3 = pk2(u1, uR0), Pu4 = pk2(uR0, uR1);

        uint64_t A = pk2(rc.x, rc.y);                    // s_t accumulator (starts at R)
        A = fma2(aSp[0], Ps0, A); A = fma2(aSp[1], Ps1, A); A = fma2(aSp[2], Ps2, A);
        A = fma2(aSp[3], Ps3, A); A = fma2(aSp[4], Ps4, A);
        uint64_t CU = bBp;                               // u-tap chain
        CU = fma2(bSp[0], Pu0, CU); CU = fma2(bSp[1], Pu1, CU); CU = fma2(bSp[2], Pu2, CU);
        CU = fma2(bSp[3], Pu3, CU); CU = fma2(bSp[4], Pu4, CU);
        uint64_t CS = fma2(bXp[0], Ps0, Z64);            // s-tap chain (independent)
        CS = fma2(bXp[1], Ps1, CS); CS = fma2(bXp[2], Ps2, CS);
        CS = fma2(bXp[3], Ps3, CS); CS = fma2(bXp[4], Ps4, CS);
        const uint64_t C = add2(CU, CS);

        float a0, a1, c0, c1;
        upk2(A, a0, a1);
        upk2(C, c0, c1);
        if (edgeW) {
            if (!inD0) { a0 = 0.f; c0 = 0.f; }
            if (!inD1) { a1 = 0.f; c1 = 0.f; }
        }
        const int sr = (t - 1) & 31;
        *reinterpret_cast<float2*>(&sm->stage[sr][stb]) = make_float2(c0, c1);
        s0 = a0; s1 = a1; u0 = c0; u1 = c1;

        rc = *ld;                                        // prefetch row t+4

        if ((t & 7) == 0) {                       // exchange epoch (no __syncthreads)
            const int buf = (t >> 3) & 1;
            if (own) {
                *reinterpret_cast<float2*>(&sm->sEx[buf][off0]) = make_float2(s0, s1);
                *reinterpret_cast<float2*>(&sm->uEx[buf][off0]) = make_float2(u0, u1);
            }
            if (remL) {                           // my first 16 own -> left CTA's right halo
                dsm_store2(&sm->sEx[buf][off0 + OWNC], rank - 1, s0, s1);
                dsm_store2(&sm->uEx[buf][off0 + OWNC], rank - 1, u0, u1);
            }
            if (remR) {                           // my last 16 own -> right CTA's left halo
                dsm_store2(&sm->sEx[buf][off0 - OWNC], rank + 1, s0, s1);
                dsm_store2(&sm->uEx[buf][off0 - OWNC], rank + 1, u0, u1);
            }
            CLUSTER_ARRIVE();                     // release: sEx/uEx + DSMEM stores
            if ((t & 15) == 0) {                  // warp-private flush overlaps the wait
                __syncwarp();
                flushw(stg, O, t - 16, w, lane, rank);
            }
            CLUSTER_WAIT();                       // acquire
            if (!own) {
                if (inD0) {
                    float2 sv = *reinterpret_cast<const float2*>(&sm->sEx[buf][off0]);
                    float2 uv = *reinterpret_cast<const float2*>(&sm->uEx[buf][off0]);
                    s0 = sv.x; u0 = uv.x;
                    if (inD1) { s1 = sv.y; u1 = uv.y; }
                } else if (inD1) {
                    s1 = sm->sEx[buf][off0 + 1]; u1 = sm->uEx[buf][off0 + 1];
                }
            }
        }
    };

    // t = 2 .. 1021, unrolled x4 (255 iterations), then 1022, 1023
    #pragma unroll 1
    for (int t = 2; t <= TT - 6; t += 4) {
        body(t,     rr0, pf);
        body(t + 1, rr1, pf + RS);
        body(t + 2, rr2, pf + 2 * RS);
        body(t + 3, rr3, pf + 3 * RS);
        pf += 4 * RS;
    }
    body(TT - 2, rr0, pf);           // prefetches padded rows 1026/1027
    body(TT - 1, rr1, pf + RS);

    // epilogue t = TT: u_{TT-1} (scalar path)
    {
        float sL2, sL1, sR0, sR1, uL2, uL1, uR0, uR1;
        HALO2(s0, s1, sL2, sL1, sR0, sR1);
        HALO2(u0, u1, uL2, uL1, uR0, uR1);
        float cu0 = bB, cu1 = bB;
        conv2acc(cu0, cu1, uL2, uL1, u0, u1, uR0, uR1, bS);
        float cs0 = 0.f, cs1 = 0.f;
        conv2acc(cs0, cs1, sL2, sL1, s0, s1, sR0, sR1, bX);
        float c0 = cu0 + cs0, c1 = cu1 + cs1;
        if (edgeW) { if (!inD0) c0 = 0.f; if (!inD1) c1 = 0.f; }
        *reinterpret_cast<float2*>(&sm->stage[31][stb]) = make_float2(c0, c1);
        __syncwarp();
        flushw(stg, O, TT - 16, w, lane, rank);
    }
}

// R[b][0][p] = pre_b + conv(pre taps, src[b][0]) ; R[b][t][p] = c_b + conv(c x-taps, src[b][t])
template <int COLTAPS, int PHASE>
__global__ void __launch_bounds__(256)
yprep(const float* __restrict__ srcparam,
      const float* __restrict__ pw, const float* __restrict__ pb,
      const float* __restrict__ cw, const float* __restrict__ cbias)
{
    const int r = blockIdx.x & (TT - 1);
    const int b = blockIdx.x >> 10;
    const float* src = (PHASE == 0 ? srcparam : (const float*)g_scr);
    const float* xr = src + ((size_t)b * TT + r) * NN;
    float* yr = g_R + ((size_t)b * TT + r) * NN;
    float tp[5], bias;
    #pragma unroll
    for (int k = 0; k < 5; ++k) {
        const int ti = COLTAPS ? (5 * k + 2) : (10 + k);
        tp[k] = (r == 0) ? pw[ti] : cw[25 + ti];
    }
    bias = (r == 0) ? pb[0] : cbias[0];
    const int p0 = threadIdx.x * 4;
    #pragma unroll
    for (int j = 0; j < 4; ++j) {
        const int p = p0 + j;
        float acc = bias;
        #pragma unroll
        for (int k = 0; k < 5; ++k) {
            const int q = p + k - 2;
            const float v = (q >= 0 && q < NN) ? __ldg(xr + q) : 0.f;
            acc = fmaf(tp[k], v, acc);
        }
        yr[p] = acc;
    }
}

extern "C" void kernel_launch(void* const* d_in, const int* in_sizes, int n_in,
                              void* d_out, int out_size)
{
    (void)in_sizes; (void)n_in; (void)out_size;
    const float* x   = (const float*)d_in[0];
    const float* p1w = (const float*)d_in[1];
    const float* p1b = (const float*)d_in[2];
    const float* p2w = (const float*)d_in[3];
    const float* p2b = (const float*)d_in[4];
    const float* p3w = (const float*)d_in[5];
    const float* p3b = (const float*)d_in[6];
    const float* p4w = (const float*)d_in[7];
    const float* p4b = (const float*)d_in[8];
    const float* c1w = (const float*)d_in[9];
    const float* c1b = (const float*)d_in[10];
    const float* c2w = (const float*)d_in[11];
    const float* c2b = (const float*)d_in[12];
    const float* c3w = (const float*)d_in[13];
    const float* c3b = (const float*)d_in[14];
    const float* c4w = (const float*)d_in[15];
    const float* c4b = (const float*)d_in[16];

    cudaFuncSetAttribute(scan_kernel<0, 0>, cudaFuncAttributeMaxDynamicSharedMemorySize, (int)sizeof(Smem));
    cudaFuncSetAttribute(scan_kernel<1, 1>, cudaFuncAttributeMaxDynamicSharedMemorySize, (int)sizeof(Smem));

    // phase A: R = pre1/c1-x conv of x rows; scan (row taps) -> g_scr
    yprep<0, 0><<<8 * TT, 256>>>(x, p1w, p1b, c1w, c1b);
    scan_kernel<0, 0><<<8 * CLC, NTH, sizeof(Smem)>>>(nullptr, p2w, p2b, c1w, c2w, c2b);
    // phase B: R = pre3/c3-x conv of scr rows; scan (col taps) -> out
    yprep<1, 1><<<8 * TT, 256>>>(nullptr, p3w, p3b, c3w, c3b);
    scan_kernel<1, 1><<<8 * CLC, NTH, sizeof(Smem)>>>((float*)d_out, p4w, p4b, c3w, c4w, c4b);
}